// round 13
// baseline (speedup 1.0000x reference)
#include <cuda_runtime.h>
#include <cuda_fp16.h>
#include <math.h>
#include <stdint.h>

#define NPIX 4096
#define CIN  512
#define CP   64
#define LOG2E 1.4426950408889634f

// ---------------- scratch ----------------
__device__ __half g_W16[3][CP * CIN];                 // Wf is pre-scaled by log2e
__device__ float  g_Wv[CIN * CP];
__device__ __half g_f[(size_t)4 * CP * NPIX];         // (b, c, i)  log2-scaled
__device__ __half g_g[(size_t)4 * CP * NPIX];         // (b, c, j)
__device__ __half g_h[(size_t)4 * CP * NPIX];         // (b, c, i)
__device__ float  g_q[4 * NPIX];                      // m2_i + log2(Z_i)
__device__ __half g_attp[(size_t)2 * 4 * NPIX * CP];  // k-split partials (fp16), (ks, b, j, c)

// ---------------- helpers ----------------
__device__ __forceinline__ uint32_t smem_u32(const void* p) {
    uint32_t a;
    asm("{ .reg .u64 t; cvta.to.shared.u64 t, %1; cvt.u32.u64 %0, t; }" : "=r"(a) : "l"(p));
    return a;
}
__device__ __forceinline__ void ldsm_x4(uint32_t* r, uint32_t a) {
    asm volatile("ldmatrix.sync.aligned.m8n8.x4.shared.b16 {%0,%1,%2,%3}, [%4];"
                 : "=r"(r[0]), "=r"(r[1]), "=r"(r[2]), "=r"(r[3]) : "r"(a));
}
__device__ __forceinline__ void ldsm_x4_t(uint32_t* r, uint32_t a) {
    asm volatile("ldmatrix.sync.aligned.m8n8.x4.trans.shared.b16 {%0,%1,%2,%3}, [%4];"
                 : "=r"(r[0]), "=r"(r[1]), "=r"(r[2]), "=r"(r[3]) : "r"(a));
}
__device__ __forceinline__ void mma16816(float* c, const uint32_t* a, uint32_t b0, uint32_t b1) {
    asm volatile("mma.sync.aligned.m16n8k16.row.col.f32.f16.f16.f32 "
                 "{%0,%1,%2,%3}, {%4,%5,%6,%7}, {%8,%9}, {%0,%1,%2,%3};"
                 : "+f"(c[0]), "+f"(c[1]), "+f"(c[2]), "+f"(c[3])
                 : "r"(a[0]), "r"(a[1]), "r"(a[2]), "r"(a[3]), "r"(b0), "r"(b1));
}
__device__ __forceinline__ uint32_t pack2(float a, float b) {
    __half2 h = __floats2half2_rn(a, b);
    return *reinterpret_cast<uint32_t*>(&h);
}
__device__ __forceinline__ uint32_t ex2h2(uint32_t d) {
    uint32_t r;
    asm("ex2.approx.f16x2 %0, %1;" : "=r"(r) : "r"(d));
    return r;
}
__device__ __forceinline__ uint32_t swz(int row, int ch, int rowB) {
    return (uint32_t)(row * rowB + ((ch ^ (row & 7)) << 4));
}
__device__ __forceinline__ void cp16(uint32_t dst, const void* src) {
    asm volatile("{ .reg .u64 g; cvta.to.global.u64 g, %1; cp.async.ca.shared.global [%0], [g], 16; }"
                 :: "r"(dst), "l"(src));
}
#define CP_COMMIT()  asm volatile("cp.async.commit_group;" ::: "memory")
#define CP_WAIT(n)   asm volatile("cp.async.wait_group %0;" :: "n"(n) : "memory")

// ---------------- spectral norm (Wf additionally scaled by log2e) ----------------
__global__ void spectral_kernel(const float* Wf, const float* Wg, const float* Wh, const float* Wv,
                                const float* uf, const float* ug, const float* uh, const float* uv)
{
    int w = blockIdx.x;
    const float* W; const float* u; int R, Cc;
    if      (w == 0) { W = Wf; u = uf; R = 64;  Cc = 512; }
    else if (w == 1) { W = Wg; u = ug; R = 64;  Cc = 512; }
    else if (w == 2) { W = Wh; u = uh; R = 64;  Cc = 512; }
    else             { W = Wv; u = uv; R = 512; Cc = 64;  }

    __shared__ float sv[512];
    __shared__ float red[512];
    __shared__ float s_scalar;
    int tid = threadIdx.x;

    float vv = 0.f;
    if (tid < Cc) {
        float s = 0.f;
        for (int r = 0; r < R; ++r) s += W[r * Cc + tid] * u[r];
        sv[tid] = s;
        vv = s * s;
    }
    red[tid] = vv;
    __syncthreads();
    for (int off = 256; off > 0; off >>= 1) {
        if (tid < off) red[tid] += red[tid + off];
        __syncthreads();
    }
    if (tid == 0) s_scalar = 1.0f / (sqrtf(red[0]) + 1e-12f);
    __syncthreads();
    if (tid < Cc) sv[tid] *= s_scalar;
    __syncthreads();

    float part = 0.f;
    if (tid < R) {
        float s = 0.f;
        for (int c = 0; c < Cc; ++c) s += W[tid * Cc + c] * sv[c];
        part = u[tid] * s;
    }
    red[tid] = part;
    __syncthreads();
    for (int off = 256; off > 0; off >>= 1) {
        if (tid < off) red[tid] += red[tid + off];
        __syncthreads();
    }
    if (tid == 0) s_scalar = 1.0f / red[0];
    __syncthreads();
    float is = s_scalar;
    if (w == 0) is *= LOG2E;
    if (w < 3) {
        for (int idx = tid; idx < R * Cc; idx += 512) g_W16[w][idx] = __float2half(W[idx] * is);
    } else {
        for (int idx = tid; idx < R * Cc; idx += 512) g_Wv[idx] = W[idx] * is;
    }
}

// ---------------- fused projections: [f;g;h] = [Wf;Wg;Wh] (192x512) @ x (512x4096) ----------------
#define PJ_SW 24576
#define PJ_SX 49152
#define PJ_SMEM 65536
__global__ __launch_bounds__(256, 1) void proj_kernel(const float* __restrict__ x)
{
    extern __shared__ char psm[];
    const int b = blockIdx.y, n0 = blockIdx.x * 128;
    const int tid = threadIdx.x, lane = tid & 31, wid = tid >> 5;
    const int mw = wid >> 1, nw = wid & 1;
    const uint32_t sb = smem_u32(psm);
    const uint32_t sXu = sb + PJ_SX;
    const float* xg = x + (size_t)b * CIN * NPIX;

    uint4 xr[4];
    {
        #pragma unroll
        for (int p = 0; p < 6; ++p) {
            int slot = tid + p * 256;
            int r = slot >> 3, ch = slot & 7;
            int w = r >> 6, cc = r & 63;
            cp16(sb + swz(r, ch, 128), g_W16[w] + cc * CIN + ch * 8);
        }
        CP_COMMIT();
        #pragma unroll
        for (int p = 0; p < 4; ++p) {
            int slot = tid + p * 256;
            int r = slot >> 4, ch = slot & 15;
            const float4* src = (const float4*)(xg + (size_t)r * NPIX + n0 + ch * 8);
            float4 f0 = src[0], f1 = src[1];
            xr[p].x = pack2(f0.x, f0.y); xr[p].y = pack2(f0.z, f0.w);
            xr[p].z = pack2(f1.x, f1.y); xr[p].w = pack2(f1.z, f1.w);
        }
    }

    float c[3][8][4] = {};
    for (int kc = 0; kc < 8; ++kc) {
        const uint32_t sWu = sb + (kc & 1) * PJ_SW;
        #pragma unroll
        for (int p = 0; p < 4; ++p) {
            int slot = tid + p * 256;
            int r = slot >> 4, ch = slot & 15;
            *(uint4*)(psm + PJ_SX + swz(r, ch, 256)) = xr[p];
        }
        if (kc + 1 < 8) {
            const uint32_t sWn = sb + ((kc + 1) & 1) * PJ_SW;
            #pragma unroll
            for (int p = 0; p < 6; ++p) {
                int slot = tid + p * 256;
                int r = slot >> 3, ch = slot & 7;
                int w = r >> 6, cc = r & 63;
                cp16(sWn + swz(r, ch, 128), g_W16[w] + cc * CIN + (kc + 1) * 64 + ch * 8);
            }
            CP_COMMIT();
            CP_WAIT(1);
        } else {
            CP_WAIT(0);
        }
        __syncthreads();
        if (kc + 1 < 8) {
            #pragma unroll
            for (int p = 0; p < 4; ++p) {
                int slot = tid + p * 256;
                int r = slot >> 4, ch = slot & 15;
                const float4* src = (const float4*)(xg + (size_t)((kc + 1) * 64 + r) * NPIX + n0 + ch * 8);
                float4 f0 = src[0], f1 = src[1];
                xr[p].x = pack2(f0.x, f0.y); xr[p].y = pack2(f0.z, f0.w);
                xr[p].z = pack2(f1.x, f1.y); xr[p].w = pack2(f1.z, f1.w);
            }
        }
        #pragma unroll
        for (int kk = 0; kk < 4; ++kk) {
            uint32_t a[3][4];
            #pragma unroll
            for (int ms = 0; ms < 3; ++ms) {
                int row = mw * 48 + ms * 16 + (lane & 7) + ((lane >> 3) & 1) * 8;
                int ch = kk * 2 + (lane >> 4);
                ldsm_x4(a[ms], sWu + swz(row, ch, 128));
            }
            #pragma unroll
            for (int ng = 0; ng < 4; ++ng) {
                int nb = nw * 64 + ng * 16;
                int row = kk * 16 + (lane & 7) + ((lane >> 3) & 1) * 8;
                int ch = (nb >> 3) + (lane >> 4);
                uint32_t bf[4];
                ldsm_x4_t(bf, sXu + swz(row, ch, 256));
                #pragma unroll
                for (int ms = 0; ms < 3; ++ms) {
                    mma16816(c[ms][ng * 2],     a[ms], bf[0], bf[1]);
                    mma16816(c[ms][ng * 2 + 1], a[ms], bf[2], bf[3]);
                }
            }
        }
        __syncthreads();
    }
    #pragma unroll
    for (int ms = 0; ms < 3; ++ms) {
        int rb = mw * 48 + ms * 16;
        int w = rb >> 6, cc = (rb & 63) + (lane >> 2);
        __half* dst = (w == 0 ? g_f : w == 1 ? g_g : g_h) + (size_t)b * CP * NPIX;
        #pragma unroll
        for (int t = 0; t < 8; ++t) {
            int col = n0 + nw * 64 + t * 8 + 2 * (lane & 3);
            *(uint32_t*)(dst + (size_t)cc * NPIX + col)       = pack2(c[ms][t][0], c[ms][t][1]);
            *(uint32_t*)(dst + (size_t)(cc + 8) * NPIX + col) = pack2(c[ms][t][2], c[ms][t][3]);
        }
    }
}

// ---------------- pass 1: online row stats (log2); i64/warp, j-chunk 256 ----------------
// dyn smem: [0) sF 8K | [8K) sG 2x32K | [72K) mz 2K
#define ST_SF 0
#define ST_SG 8192
#define ST_MZ 73728
#define ST_SMEM 75776
__global__ __launch_bounds__(128, 2) void stats_kernel()
{
    extern __shared__ char smem[];
    const int b = blockIdx.y, i0 = blockIdx.x * 64;
    const int tid = threadIdx.x, lane = tid & 31, nw = tid >> 5;   // 4 warps = j32 stripes
    const uint32_t sb = smem_u32(smem);
    const uint32_t sFu = sb + ST_SF;
    const uint32_t sGu0 = sb + ST_SG, sGu1 = sb + ST_SG + 32768;
    float* mz = (float*)(smem + ST_MZ);                 // [nw][2][64]
    const __half* F = g_f + (size_t)b * CP * NPIX;
    const __half* G = g_g + (size_t)b * CP * NPIX;

    // F tile once (c64 x i64, rowB 128)
    #pragma unroll
    for (int p = 0; p < 4; ++p) {
        int slot = tid + p * 128;
        int r = slot >> 3, ch = slot & 7;
        uint4 v = *(const uint4*)(F + (size_t)r * NPIX + i0 + ch * 8);
        *(uint4*)(smem + ST_SF + swz(r, ch, 128)) = v;
    }
    // G chunk 0 (c64 x j256, rowB 512): 2048 uint4
    #pragma unroll
    for (int p = 0; p < 16; ++p) {
        int slot = tid + p * 128;
        int r = slot >> 5, ch = slot & 31;
        cp16(sGu0 + swz(r, ch, 512), G + (size_t)r * NPIX + ch * 8);
    }
    CP_COMMIT();
    __syncthreads();

    // A-frags for ALL i64 rows (held in registers)
    uint32_t afr[4][4][4];
    #pragma unroll
    for (int ms = 0; ms < 4; ++ms)
        #pragma unroll
        for (int kk = 0; kk < 4; ++kk) {
            int row = kk * 16 + (lane & 7) + ((lane >> 4) & 1) * 8;
            int ch = (ms * 16 >> 3) + ((lane >> 3) & 1);
            ldsm_x4_t(afr[ms][kk], sFu + swz(row, ch, 128));
        }

    float m[8], z[8] = {0.f, 0.f, 0.f, 0.f, 0.f, 0.f, 0.f, 0.f};
    #pragma unroll
    for (int q = 0; q < 8; ++q) m[q] = -INFINITY;

    for (int jc = 0; jc < 16; ++jc) {                   // j-chunks of 256
        const int j0 = jc * 256;
        if (jc + 1 < 16) {
            uint32_t dstb = (jc & 1) ? sGu0 : sGu1;
            #pragma unroll
            for (int p = 0; p < 16; ++p) {
                int slot = tid + p * 128;
                int r = slot >> 5, ch = slot & 31;
                cp16(dstb + swz(r, ch, 512), G + (size_t)r * NPIX + (j0 + 256) + ch * 8);
            }
            CP_COMMIT();
            CP_WAIT(1);
        } else {
            CP_WAIT(0);
        }
        __syncthreads();
        const uint32_t sGu = (jc & 1) ? sGu1 : sGu0;

        #pragma unroll
        for (int jh = 0; jh < 2; ++jh) {                // two j128 halves
            float c[4][4][4] = {};
            #pragma unroll
            for (int kk = 0; kk < 4; ++kk) {
                #pragma unroll
                for (int ng = 0; ng < 2; ++ng) {
                    int nb = jh * 128 + nw * 32 + ng * 16;
                    int row = kk * 16 + (lane & 7) + ((lane >> 3) & 1) * 8;
                    int ch = (nb >> 3) + (lane >> 4);
                    uint32_t bf[4];
                    ldsm_x4_t(bf, sGu + swz(row, ch, 512));
                    #pragma unroll
                    for (int ms = 0; ms < 4; ++ms) {
                        mma16816(c[ms][ng * 2],     afr[ms][kk], bf[0], bf[1]);
                        mma16816(c[ms][ng * 2 + 1], afr[ms][kk], bf[2], bf[3]);
                    }
                }
            }
            float cm[8];
            #pragma unroll
            for (int ms = 0; ms < 4; ++ms) {
                float a0 = fmaxf(fmaxf(c[ms][0][0], c[ms][0][1]), fmaxf(c[ms][1][0], c[ms][1][1]));
                float a1 = fmaxf(fmaxf(c[ms][2][0], c[ms][2][1]), fmaxf(c[ms][3][0], c[ms][3][1]));
                cm[ms * 2] = fmaxf(a0, a1);
                float b0 = fmaxf(fmaxf(c[ms][0][2], c[ms][0][3]), fmaxf(c[ms][1][2], c[ms][1][3]));
                float b1 = fmaxf(fmaxf(c[ms][2][2], c[ms][2][3]), fmaxf(c[ms][3][2], c[ms][3][3]));
                cm[ms * 2 + 1] = fmaxf(b0, b1);
            }
            #pragma unroll
            for (int q = 0; q < 8; ++q) {
                cm[q] = fmaxf(cm[q], __shfl_xor_sync(0xffffffffu, cm[q], 1));
                cm[q] = fmaxf(cm[q], __shfl_xor_sync(0xffffffffu, cm[q], 2));
                float mnew = fmaxf(m[q], cm[q]);
                z[q] *= exp2f(m[q] - mnew);
                m[q] = mnew;
            }
            #pragma unroll
            for (int ms = 0; ms < 4; ++ms) {
                #pragma unroll
                for (int nt = 0; nt < 4; ++nt) {
                    uint32_t e0 = ex2h2(pack2(c[ms][nt][0] - m[ms * 2],     c[ms][nt][1] - m[ms * 2]));
                    uint32_t e1 = ex2h2(pack2(c[ms][nt][2] - m[ms * 2 + 1], c[ms][nt][3] - m[ms * 2 + 1]));
                    float2 f0 = __half22float2(*reinterpret_cast<__half2*>(&e0));
                    float2 f1 = __half22float2(*reinterpret_cast<__half2*>(&e1));
                    z[ms * 2]     += f0.x + f0.y;
                    z[ms * 2 + 1] += f1.x + f1.y;
                }
            }
        }
        __syncthreads();
    }
    if ((lane & 3) == 0) {
        #pragma unroll
        for (int q = 0; q < 8; ++q) {
            int row = (q >> 1) * 16 + (lane >> 2) + (q & 1) * 8;
            mz[(nw * 2 + 0) * 64 + row] = m[q];
            mz[(nw * 2 + 1) * 64 + row] = z[q];
        }
    }
    __syncthreads();
    if (tid < 64) {
        float m0 = mz[0 * 64 + tid], m1 = mz[2 * 64 + tid], m2 = mz[4 * 64 + tid], m3 = mz[6 * 64 + tid];
        float mf = fmaxf(fmaxf(m0, m1), fmaxf(m2, m3));
        float Z = mz[1 * 64 + tid] * exp2f(m0 - mf) + mz[3 * 64 + tid] * exp2f(m1 - mf)
                + mz[5 * 64 + tid] * exp2f(m2 - mf) + mz[7 * 64 + tid] * exp2f(m3 - mf);
        g_q[b * NPIX + i0 + tid] = mf + __log2f(Z);
    }
}

// ---------------- pass 2 (k-split): j32/warp, i-chunk 128 (two i64 halves/barrier) ----------------
// dyn smem: [0) sG 16K | [16K) sF 2x16K | [48K) sH 2x16K | [80K) q 2x512B
#define PV_SG 0
#define PV_SF 16384
#define PV_SH 49152
#define PV_SQ 81920
#define PV_SMEM 82944
__global__ __launch_bounds__(128, 2) void pv_kernel()
{
    extern __shared__ char smem[];
    const int b = blockIdx.y, j0 = blockIdx.x * 128, ksp = blockIdx.z;
    const int ibase = ksp * 2048;
    const int tid = threadIdx.x, lane = tid & 31, wid = tid >> 5;   // 4 warps, j32 each
    const uint32_t sb = smem_u32(smem);
    const __half* F = g_f + (size_t)b * CP * NPIX;
    const __half* G = g_g + (size_t)b * CP * NPIX;
    const __half* H = g_h + (size_t)b * CP * NPIX;
    const float* Q = g_q + b * NPIX;

    // prologue: i-chunk 0 (c64 x i128, rowB 256) for F and H; q 128 floats
    {
        uint32_t sf = sb + PV_SF, sh = sb + PV_SH;
        #pragma unroll
        for (int p = 0; p < 8; ++p) {
            int slot = tid + p * 128;
            int r = slot >> 4, ch = slot & 15;
            cp16(sf + swz(r, ch, 256), F + (size_t)r * NPIX + ibase + ch * 8);
            cp16(sh + swz(r, ch, 256), H + (size_t)r * NPIX + ibase + ch * 8);
        }
        if (tid < 32) cp16(sb + PV_SQ + tid * 16, Q + ibase + tid * 4);
        CP_COMMIT();
    }
    // G tile c64 x j128, rowB 256
    #pragma unroll
    for (int p = 0; p < 8; ++p) {
        int slot = tid + p * 128;
        int r = slot >> 4, ch = slot & 15;
        uint4 v = *(const uint4*)(G + (size_t)r * NPIX + j0 + ch * 8);
        *(uint4*)(smem + PV_SG + swz(r, ch, 256)) = v;
    }

    float ot[2][8][4] = {};
    for (int it = 0; it < 16; ++it) {
        const int cur = it & 1;
        if (it + 1 < 16) {
            const int i1 = ibase + (it + 1) * 128, nxt = cur ^ 1;
            uint32_t sf = sb + PV_SF + nxt * 16384, sh = sb + PV_SH + nxt * 16384;
            #pragma unroll
            for (int p = 0; p < 8; ++p) {
                int slot = tid + p * 128;
                int r = slot >> 4, ch = slot & 15;
                cp16(sf + swz(r, ch, 256), F + (size_t)r * NPIX + i1 + ch * 8);
                cp16(sh + swz(r, ch, 256), H + (size_t)r * NPIX + i1 + ch * 8);
            }
            if (tid < 32) cp16(sb + PV_SQ + nxt * 512 + tid * 16, Q + i1 + tid * 4);
            CP_COMMIT();
            CP_WAIT(1);
        } else {
            CP_WAIT(0);
        }
        __syncthreads();

        const uint32_t sFu = sb + PV_SF + cur * 16384;
        const uint32_t sHu = sb + PV_SH + cur * 16384;
        const float* sq = (const float*)(smem + PV_SQ + cur * 512);

        #pragma unroll
        for (int ic2 = 0; ic2 < 2; ++ic2) {             // two i64 halves per chunk
            // MMA1: St[j32, i64] = g^T f
            float st[2][8][4] = {};
            #pragma unroll
            for (int kk = 0; kk < 4; ++kk) {
                uint32_t agg[2][4];
                #pragma unroll
                for (int jh = 0; jh < 2; ++jh) {
                    int row = kk * 16 + (lane & 7) + ((lane >> 4) & 1) * 8;
                    int ch = ((wid * 32 + jh * 16) >> 3) + ((lane >> 3) & 1);
                    ldsm_x4_t(agg[jh], sb + PV_SG + swz(row, ch, 256));
                }
                #pragma unroll
                for (int ng = 0; ng < 4; ++ng) {
                    int row = kk * 16 + (lane & 7) + ((lane >> 3) & 1) * 8;
                    int ch = ic2 * 8 + ng * 2 + (lane >> 4);
                    uint32_t bf[4];
                    ldsm_x4_t(bf, sFu + swz(row, ch, 256));
                    #pragma unroll
                    for (int jh = 0; jh < 2; ++jh) {
                        mma16816(st[jh][ng * 2],     agg[jh], bf[0], bf[1]);
                        mma16816(st[jh][ng * 2 + 1], agg[jh], bf[2], bf[3]);
                    }
                }
            }
            // attn = exp2(St - q_i): fp16x2, directly the A-frags
            uint32_t aet[2][4][4];
            #pragma unroll
            for (int jh = 0; jh < 2; ++jh) {
                #pragma unroll
                for (int t = 0; t < 8; ++t) {
                    int col = ic2 * 64 + t * 8 + 2 * (lane & 3);
                    float q0 = sq[col], q1 = sq[col + 1];
                    uint32_t lo = ex2h2(pack2(st[jh][t][0] - q0, st[jh][t][1] - q1));
                    uint32_t hi = ex2h2(pack2(st[jh][t][2] - q0, st[jh][t][3] - q1));
                    aet[jh][t >> 1][(t & 1) * 2]     = lo;
                    aet[jh][t >> 1][(t & 1) * 2 + 1] = hi;
                }
            }
            // MMA2: Ot[j32, c64] += attn @ h^T
            #pragma unroll
            for (int kt = 0; kt < 4; ++kt) {
                #pragma unroll
                for (int cg = 0; cg < 4; ++cg) {
                    int row = cg * 16 + ((lane >> 4) & 1) * 8 + (lane & 7);
                    int ch = ic2 * 8 + kt * 2 + ((lane >> 3) & 1);
                    uint32_t bh[4];
                    ldsm_x4(bh, sHu + swz(row, ch, 256));
                    #pragma unroll
                    for (int jh = 0; jh < 2; ++jh) {
                        mma16816(ot[jh][cg * 2],     aet[jh][kt], bh[0], bh[1]);
                        mma16816(ot[jh][cg * 2 + 1], aet[jh][kt], bh[2], bh[3]);
                    }
                }
            }
        }
        __syncthreads();
    }
    #pragma unroll
    for (int jh = 0; jh < 2; ++jh) {
        int j = j0 + wid * 32 + jh * 16 + (lane >> 2);
        __half* dst = g_attp + ((size_t)(ksp * 4 + b) * NPIX + j) * CP;
        #pragma unroll
        for (int t = 0; t < 8; ++t) {
            int c = t * 8 + 2 * (lane & 3);
            *(uint32_t*)(dst + c)          = pack2(ot[jh][t][0], ot[jh][t][1]);
            *(uint32_t*)(dst + 8 * CP + c) = pack2(ot[jh][t][2], ot[jh][t][3]);
        }
    }
}

// ---------------- final: y = gamma * (Wv_sn @ (P0+P1)) + x, fp16 partials ----------------
__global__ __launch_bounds__(256) void final_kernel(const float* __restrict__ x,
                                                    const float* __restrict__ gamma,
                                                    float* __restrict__ y)
{
    int b  = blockIdx.z;
    int c0 = blockIdx.y * 64;
    int n0 = blockIdx.x * 64;
    const float* A    = g_Wv;
    const __half* Bv0 = g_attp + (size_t)b * NPIX * CP;
    const __half* Bv1 = g_attp + (size_t)(4 + b) * NPIX * CP;

    __shared__ float As[32][65];
    __shared__ float Bs[32][65];
    int tid = threadIdx.x;
    int ty = tid >> 4, tx = tid & 15;
    float acc[4][4] = {};

    for (int k0 = 0; k0 < 64; k0 += 32) {
        #pragma unroll
        for (int t = 0; t < 8; ++t) {
            int idx = tid + t * 256;
            int m = idx >> 5, k = idx & 31;
            As[k][m] = A[(c0 + m) * 64 + k0 + k];
        }
        #pragma unroll
        for (int t = 0; t < 2; ++t) {
            int idx = tid + t * 256;
            int n = idx >> 3, k4 = (idx & 7) * 4;
            size_t off = (size_t)(n0 + n) * CP + k0 + k4;
            uint2 u0 = *(const uint2*)(Bv0 + off);
            uint2 u1 = *(const uint2*)(Bv1 + off);
            float2 a0 = __half22float2(*reinterpret_cast<__half2*>(&u0.x));
            float2 a1 = __half22float2(*reinterpret_cast<__half2*>(&u0.y));
            float2 b0 = __half22float2(*reinterpret_cast<__half2*>(&u1.x));
            float2 b1 = __half22float2(*reinterpret_cast<__half2*>(&u1.y));
            Bs[k4][n]     = a0.x + b0.x;
            Bs[k4 + 1][n] = a0.y + b0.y;
            Bs[k4 + 2][n] = a1.x + b1.x;
            Bs[k4 + 3][n] = a1.y + b1.y;
        }
        __syncthreads();
        #pragma unroll
        for (int kk = 0; kk < 32; ++kk) {
            float a[4], bb[4];
            #pragma unroll
            for (int i = 0; i < 4; ++i) { a[i] = As[kk][ty * 4 + i]; bb[i] = Bs[kk][tx * 4 + i]; }
            #pragma unroll
            for (int mi = 0; mi < 4; ++mi)
                #pragma unroll
                for (int ni = 0; ni < 4; ++ni)
                    acc[mi][ni] = fmaf(a[mi], bb[ni], acc[mi][ni]);
        }
        __syncthreads();
    }
    float g = gamma[0];
    #pragma unroll
    for (int mi = 0; mi < 4; ++mi) {
        size_t o = (size_t)b * CIN * NPIX + (size_t)(c0 + ty * 4 + mi) * NPIX + n0 + tx * 4;
        float4 xv = *(const float4*)(x + o);
        float4 r;
        r.x = fmaf(g, acc[mi][0], xv.x);
        r.y = fmaf(g, acc[mi][1], xv.y);
        r.z = fmaf(g, acc[mi][2], xv.z);
        r.w = fmaf(g, acc[mi][3], xv.w);
        *(float4*)(y + o) = r;
    }
}

// ---------------- launch ----------------
extern "C" void kernel_launch(void* const* d_in, const int* in_sizes, int n_in,
                              void* d_out, int out_size)
{
    const float* x     = (const float*)d_in[0];
    const float* Wf    = (const float*)d_in[1];
    const float* Wg    = (const float*)d_in[2];
    const float* Wh    = (const float*)d_in[3];
    const float* Wv    = (const float*)d_in[4];
    const float* uf    = (const float*)d_in[5];
    const float* ug    = (const float*)d_in[6];
    const float* uh    = (const float*)d_in[7];
    const float* uv    = (const float*)d_in[8];
    const float* gamma = (const float*)d_in[9];
    float* y = (float*)d_out;

    cudaFuncSetAttribute(proj_kernel,  cudaFuncAttributeMaxDynamicSharedMemorySize, PJ_SMEM);
    cudaFuncSetAttribute(stats_kernel, cudaFuncAttributeMaxDynamicSharedMemorySize, ST_SMEM);
    cudaFuncSetAttribute(pv_kernel,    cudaFuncAttributeMaxDynamicSharedMemorySize, PV_SMEM);

    spectral_kernel<<<4, 512>>>(Wf, Wg, Wh, Wv, uf, ug, uh, uv);
    proj_kernel<<<dim3(32, 4), 256, PJ_SMEM>>>(x);
    stats_kernel<<<dim3(64, 4), 128, ST_SMEM>>>();
    pv_kernel<<<dim3(32, 4, 2), 128, PV_SMEM>>>();
    final_kernel<<<dim3(64, 8, 4), 256>>>(x, gamma, y);
}

// round 15
// speedup vs baseline: 1.1644x; 1.1644x over previous
#include <cuda_runtime.h>
#include <cuda_fp16.h>
#include <math.h>
#include <stdint.h>

#define NPIX 4096
#define CIN  512
#define CP   64
#define LOG2E 1.4426950408889634f

// ---------------- scratch ----------------
__device__ __half g_W16[3][CP * CIN];                 // Wf is pre-scaled by log2e
__device__ __half g_Wv16[CIN * CP];                   // fp16 Wv_sn, (c, k) rows
__device__ __half g_f[(size_t)4 * CP * NPIX];         // (b, c, i)  log2-scaled
__device__ __half g_g[(size_t)4 * CP * NPIX];         // (b, c, j)
__device__ __half g_h[(size_t)4 * CP * NPIX];         // (b, c, i)
__device__ float  g_q[4 * NPIX];                      // m2_i + log2(Z_i)
__device__ __half g_attp[(size_t)2 * 4 * NPIX * CP];  // k-split partials (fp16), (ks, b, j, c)

// ---------------- helpers ----------------
__device__ __forceinline__ uint32_t smem_u32(const void* p) {
    uint32_t a;
    asm("{ .reg .u64 t; cvta.to.shared.u64 t, %1; cvt.u32.u64 %0, t; }" : "=r"(a) : "l"(p));
    return a;
}
__device__ __forceinline__ void ldsm_x4(uint32_t* r, uint32_t a) {
    asm volatile("ldmatrix.sync.aligned.m8n8.x4.shared.b16 {%0,%1,%2,%3}, [%4];"
                 : "=r"(r[0]), "=r"(r[1]), "=r"(r[2]), "=r"(r[3]) : "r"(a));
}
__device__ __forceinline__ void ldsm_x4_t(uint32_t* r, uint32_t a) {
    asm volatile("ldmatrix.sync.aligned.m8n8.x4.trans.shared.b16 {%0,%1,%2,%3}, [%4];"
                 : "=r"(r[0]), "=r"(r[1]), "=r"(r[2]), "=r"(r[3]) : "r"(a));
}
__device__ __forceinline__ void mma16816(float* c, const uint32_t* a, uint32_t b0, uint32_t b1) {
    asm volatile("mma.sync.aligned.m16n8k16.row.col.f32.f16.f16.f32 "
                 "{%0,%1,%2,%3}, {%4,%5,%6,%7}, {%8,%9}, {%0,%1,%2,%3};"
                 : "+f"(c[0]), "+f"(c[1]), "+f"(c[2]), "+f"(c[3])
                 : "r"(a[0]), "r"(a[1]), "r"(a[2]), "r"(a[3]), "r"(b0), "r"(b1));
}
__device__ __forceinline__ uint32_t pack2(float a, float b) {
    __half2 h = __floats2half2_rn(a, b);
    return *reinterpret_cast<uint32_t*>(&h);
}
__device__ __forceinline__ uint32_t ex2h2(uint32_t d) {
    uint32_t r;
    asm("ex2.approx.f16x2 %0, %1;" : "=r"(r) : "r"(d));
    return r;
}
__device__ __forceinline__ uint32_t swz(int row, int ch, int rowB) {
    return (uint32_t)(row * rowB + ((ch ^ (row & 7)) << 4));
}
__device__ __forceinline__ void cp16(uint32_t dst, const void* src) {
    asm volatile("{ .reg .u64 g; cvta.to.global.u64 g, %1; cp.async.ca.shared.global [%0], [g], 16; }"
                 :: "r"(dst), "l"(src));
}
#define CP_COMMIT()  asm volatile("cp.async.commit_group;" ::: "memory")
#define CP_WAIT(n)   asm volatile("cp.async.wait_group %0;" :: "n"(n) : "memory")

// ---------------- spectral norm (Wf additionally scaled by log2e) ----------------
__global__ void spectral_kernel(const float* Wf, const float* Wg, const float* Wh, const float* Wv,
                                const float* uf, const float* ug, const float* uh, const float* uv)
{
    int w = blockIdx.x;
    const float* W; const float* u; int R, Cc;
    if      (w == 0) { W = Wf; u = uf; R = 64;  Cc = 512; }
    else if (w == 1) { W = Wg; u = ug; R = 64;  Cc = 512; }
    else if (w == 2) { W = Wh; u = uh; R = 64;  Cc = 512; }
    else             { W = Wv; u = uv; R = 512; Cc = 64;  }

    __shared__ float sv[512];
    __shared__ float red[512];
    __shared__ float s_scalar;
    int tid = threadIdx.x;

    float vv = 0.f;
    if (tid < Cc) {
        float s = 0.f;
        for (int r = 0; r < R; ++r) s += W[r * Cc + tid] * u[r];
        sv[tid] = s;
        vv = s * s;
    }
    red[tid] = vv;
    __syncthreads();
    for (int off = 256; off > 0; off >>= 1) {
        if (tid < off) red[tid] += red[tid + off];
        __syncthreads();
    }
    if (tid == 0) s_scalar = 1.0f / (sqrtf(red[0]) + 1e-12f);
    __syncthreads();
    if (tid < Cc) sv[tid] *= s_scalar;
    __syncthreads();

    float part = 0.f;
    if (tid < R) {
        float s = 0.f;
        for (int c = 0; c < Cc; ++c) s += W[tid * Cc + c] * sv[c];
        part = u[tid] * s;
    }
    red[tid] = part;
    __syncthreads();
    for (int off = 256; off > 0; off >>= 1) {
        if (tid < off) red[tid] += red[tid + off];
        __syncthreads();
    }
    if (tid == 0) s_scalar = 1.0f / red[0];
    __syncthreads();
    float is = s_scalar;
    if (w == 0) is *= LOG2E;
    if (w < 3) {
        for (int idx = tid; idx < R * Cc; idx += 512) g_W16[w][idx] = __float2half(W[idx] * is);
    } else {
        for (int idx = tid; idx < R * Cc; idx += 512) g_Wv16[idx] = __float2half(W[idx] * is);
    }
}

// ---------------- fused projections: [f;g;h] = [Wf;Wg;Wh] (192x512) @ x (512x4096) ----------------
#define PJ_SW 24576
#define PJ_SX 49152
#define PJ_SMEM 65536
__global__ __launch_bounds__(256, 1) void proj_kernel(const float* __restrict__ x)
{
    extern __shared__ char psm[];
    const int b = blockIdx.y, n0 = blockIdx.x * 128;
    const int tid = threadIdx.x, lane = tid & 31, wid = tid >> 5;
    const int mw = wid >> 1, nw = wid & 1;
    const uint32_t sb = smem_u32(psm);
    const uint32_t sXu = sb + PJ_SX;
    const float* xg = x + (size_t)b * CIN * NPIX;

    uint4 xr[4];
    {
        #pragma unroll
        for (int p = 0; p < 6; ++p) {
            int slot = tid + p * 256;
            int r = slot >> 3, ch = slot & 7;
            int w = r >> 6, cc = r & 63;
            cp16(sb + swz(r, ch, 128), g_W16[w] + cc * CIN + ch * 8);
        }
        CP_COMMIT();
        #pragma unroll
        for (int p = 0; p < 4; ++p) {
            int slot = tid + p * 256;
            int r = slot >> 4, ch = slot & 15;
            const float4* src = (const float4*)(xg + (size_t)r * NPIX + n0 + ch * 8);
            float4 f0 = src[0], f1 = src[1];
            xr[p].x = pack2(f0.x, f0.y); xr[p].y = pack2(f0.z, f0.w);
            xr[p].z = pack2(f1.x, f1.y); xr[p].w = pack2(f1.z, f1.w);
        }
    }

    float c[3][8][4] = {};
    for (int kc = 0; kc < 8; ++kc) {
        const uint32_t sWu = sb + (kc & 1) * PJ_SW;
        #pragma unroll
        for (int p = 0; p < 4; ++p) {
            int slot = tid + p * 256;
            int r = slot >> 4, ch = slot & 15;
            *(uint4*)(psm + PJ_SX + swz(r, ch, 256)) = xr[p];
        }
        if (kc + 1 < 8) {
            const uint32_t sWn = sb + ((kc + 1) & 1) * PJ_SW;
            #pragma unroll
            for (int p = 0; p < 6; ++p) {
                int slot = tid + p * 256;
                int r = slot >> 3, ch = slot & 7;
                int w = r >> 6, cc = r & 63;
                cp16(sWn + swz(r, ch, 128), g_W16[w] + cc * CIN + (kc + 1) * 64 + ch * 8);
            }
            CP_COMMIT();
            CP_WAIT(1);
        } else {
            CP_WAIT(0);
        }
        __syncthreads();
        if (kc + 1 < 8) {
            #pragma unroll
            for (int p = 0; p < 4; ++p) {
                int slot = tid + p * 256;
                int r = slot >> 4, ch = slot & 15;
                const float4* src = (const float4*)(xg + (size_t)((kc + 1) * 64 + r) * NPIX + n0 + ch * 8);
                float4 f0 = src[0], f1 = src[1];
                xr[p].x = pack2(f0.x, f0.y); xr[p].y = pack2(f0.z, f0.w);
                xr[p].z = pack2(f1.x, f1.y); xr[p].w = pack2(f1.z, f1.w);
            }
        }
        #pragma unroll
        for (int kk = 0; kk < 4; ++kk) {
            uint32_t a[3][4];
            #pragma unroll
            for (int ms = 0; ms < 3; ++ms) {
                int row = mw * 48 + ms * 16 + (lane & 7) + ((lane >> 3) & 1) * 8;
                int ch = kk * 2 + (lane >> 4);
                ldsm_x4(a[ms], sWu + swz(row, ch, 128));
            }
            #pragma unroll
            for (int ng = 0; ng < 4; ++ng) {
                int nb = nw * 64 + ng * 16;
                int row = kk * 16 + (lane & 7) + ((lane >> 3) & 1) * 8;
                int ch = (nb >> 3) + (lane >> 4);
                uint32_t bf[4];
                ldsm_x4_t(bf, sXu + swz(row, ch, 256));
                #pragma unroll
                for (int ms = 0; ms < 3; ++ms) {
                    mma16816(c[ms][ng * 2],     a[ms], bf[0], bf[1]);
                    mma16816(c[ms][ng * 2 + 1], a[ms], bf[2], bf[3]);
                }
            }
        }
        __syncthreads();
    }
    #pragma unroll
    for (int ms = 0; ms < 3; ++ms) {
        int rb = mw * 48 + ms * 16;
        int w = rb >> 6, cc = (rb & 63) + (lane >> 2);
        __half* dst = (w == 0 ? g_f : w == 1 ? g_g : g_h) + (size_t)b * CP * NPIX;
        #pragma unroll
        for (int t = 0; t < 8; ++t) {
            int col = n0 + nw * 64 + t * 8 + 2 * (lane & 3);
            *(uint32_t*)(dst + (size_t)cc * NPIX + col)       = pack2(c[ms][t][0], c[ms][t][1]);
            *(uint32_t*)(dst + (size_t)(cc + 8) * NPIX + col) = pack2(c[ms][t][2], c[ms][t][3]);
        }
    }
}

// ---------------- pass 1: online row stats (log2); i64 PER WARP, 4 warps ----------------
__global__ __launch_bounds__(128, 2) void stats_kernel()
{
    __shared__ __align__(16) __half sF[64 * 64];        // 8KB, c64 x i64
    __shared__ __align__(16) __half sG[2][64 * 128];    // 2x16KB, c64 x j128
    __shared__ float s_mz[4][2][64];
    const int b = blockIdx.y, i0 = blockIdx.x * 64;
    const int tid = threadIdx.x, lane = tid & 31, nw = tid >> 5;   // 4 warps = j32 stripes
    const uint32_t sFu = smem_u32(sF);
    const uint32_t sGu0 = smem_u32(sG[0]), sGu1 = smem_u32(sG[1]);
    const __half* F = g_f + (size_t)b * CP * NPIX;
    const __half* G = g_g + (size_t)b * CP * NPIX;

    #pragma unroll
    for (int p = 0; p < 4; ++p) {
        int slot = tid + p * 128;
        int r = slot >> 3, ch = slot & 7;
        uint4 v = *(const uint4*)(F + (size_t)r * NPIX + i0 + ch * 8);
        *(uint4*)((char*)sF + swz(r, ch, 128)) = v;
    }
    #pragma unroll
    for (int p = 0; p < 8; ++p) {
        int slot = tid + p * 128;
        int r = slot >> 4, ch = slot & 15;
        cp16(sGu0 + swz(r, ch, 256), G + (size_t)r * NPIX + ch * 8);
    }
    CP_COMMIT();
    __syncthreads();

    uint32_t afr[4][4][4];
    #pragma unroll
    for (int ms = 0; ms < 4; ++ms)
        #pragma unroll
        for (int kk = 0; kk < 4; ++kk) {
            int row = kk * 16 + (lane & 7) + ((lane >> 4) & 1) * 8;
            int ch = (ms * 16 >> 3) + ((lane >> 3) & 1);
            ldsm_x4_t(afr[ms][kk], sFu + swz(row, ch, 128));
        }

    float m[8], z[8] = {0.f, 0.f, 0.f, 0.f, 0.f, 0.f, 0.f, 0.f};
    #pragma unroll
    for (int q = 0; q < 8; ++q) m[q] = -INFINITY;

    for (int jc = 0; jc < 32; ++jc) {
        const int j0 = jc * 128;
        if (jc + 1 < 32) {
            uint32_t dstb = (jc & 1) ? sGu0 : sGu1;
            #pragma unroll
            for (int p = 0; p < 8; ++p) {
                int slot = tid + p * 128;
                int r = slot >> 4, ch = slot & 15;
                cp16(dstb + swz(r, ch, 256), G + (size_t)r * NPIX + (j0 + 128) + ch * 8);
            }
            CP_COMMIT();
            CP_WAIT(1);
        } else {
            CP_WAIT(0);
        }
        __syncthreads();
        const uint32_t sGu = (jc & 1) ? sGu1 : sGu0;

        float c[4][4][4] = {};
        #pragma unroll
        for (int kk = 0; kk < 4; ++kk) {
            #pragma unroll
            for (int ng = 0; ng < 2; ++ng) {
                int nb = nw * 32 + ng * 16;
                int row = kk * 16 + (lane & 7) + ((lane >> 3) & 1) * 8;
                int ch = (nb >> 3) + (lane >> 4);
                uint32_t bf[4];
                ldsm_x4_t(bf, sGu + swz(row, ch, 256));
                #pragma unroll
                for (int ms = 0; ms < 4; ++ms) {
                    mma16816(c[ms][ng * 2],     afr[ms][kk], bf[0], bf[1]);
                    mma16816(c[ms][ng * 2 + 1], afr[ms][kk], bf[2], bf[3]);
                }
            }
        }
        float cm[8];
        #pragma unroll
        for (int ms = 0; ms < 4; ++ms) {
            float a0 = fmaxf(fmaxf(c[ms][0][0], c[ms][0][1]), fmaxf(c[ms][1][0], c[ms][1][1]));
            float a1 = fmaxf(fmaxf(c[ms][2][0], c[ms][2][1]), fmaxf(c[ms][3][0], c[ms][3][1]));
            cm[ms * 2] = fmaxf(a0, a1);
            float b0 = fmaxf(fmaxf(c[ms][0][2], c[ms][0][3]), fmaxf(c[ms][1][2], c[ms][1][3]));
            float b1 = fmaxf(fmaxf(c[ms][2][2], c[ms][2][3]), fmaxf(c[ms][3][2], c[ms][3][3]));
            cm[ms * 2 + 1] = fmaxf(b0, b1);
        }
        #pragma unroll
        for (int q = 0; q < 8; ++q) {
            cm[q] = fmaxf(cm[q], __shfl_xor_sync(0xffffffffu, cm[q], 1));
            cm[q] = fmaxf(cm[q], __shfl_xor_sync(0xffffffffu, cm[q], 2));
            float mnew = fmaxf(m[q], cm[q]);
            z[q] *= exp2f(m[q] - mnew);
            m[q] = mnew;
        }
        #pragma unroll
        for (int ms = 0; ms < 4; ++ms) {
            #pragma unroll
            for (int nt = 0; nt < 4; ++nt) {
                uint32_t e0 = ex2h2(pack2(c[ms][nt][0] - m[ms * 2],     c[ms][nt][1] - m[ms * 2]));
                uint32_t e1 = ex2h2(pack2(c[ms][nt][2] - m[ms * 2 + 1], c[ms][nt][3] - m[ms * 2 + 1]));
                float2 f0 = __half22float2(*reinterpret_cast<__half2*>(&e0));
                float2 f1 = __half22float2(*reinterpret_cast<__half2*>(&e1));
                z[ms * 2]     += f0.x + f0.y;
                z[ms * 2 + 1] += f1.x + f1.y;
            }
        }
        __syncthreads();
    }
    if ((lane & 3) == 0) {
        #pragma unroll
        for (int q = 0; q < 8; ++q) {
            int row = (q >> 1) * 16 + (lane >> 2) + (q & 1) * 8;
            s_mz[nw][0][row] = m[q];
            s_mz[nw][1][row] = z[q];
        }
    }
    __syncthreads();
    if (tid < 64) {
        float m0 = s_mz[0][0][tid], m1 = s_mz[1][0][tid], m2 = s_mz[2][0][tid], m3 = s_mz[3][0][tid];
        float mf = fmaxf(fmaxf(m0, m1), fmaxf(m2, m3));
        float Z = s_mz[0][1][tid] * exp2f(m0 - mf) + s_mz[1][1][tid] * exp2f(m1 - mf)
                + s_mz[2][1][tid] * exp2f(m2 - mf) + s_mz[3][1][tid] * exp2f(m3 - mf);
        g_q[b * NPIX + i0 + tid] = mf + __log2f(Z);
    }
}

// ---------------- pass 2 (k-split): j32 PER WARP, 4 warps, j-tile 128 ----------------
#define PV_SG 0
#define PV_SF 16384
#define PV_SH 32768
#define PV_SQ 49152
#define PV_SMEM 49664
__global__ __launch_bounds__(128, 2) void pv_kernel()
{
    extern __shared__ char smem[];
    const int b = blockIdx.y, j0 = blockIdx.x * 128, ksp = blockIdx.z;
    const int ibase = ksp * 2048;
    const int tid = threadIdx.x, lane = tid & 31, wid = tid >> 5;
    const uint32_t sb = smem_u32(smem);
    const __half* F = g_f + (size_t)b * CP * NPIX;
    const __half* G = g_g + (size_t)b * CP * NPIX;
    const __half* H = g_h + (size_t)b * CP * NPIX;
    const float* Q = g_q + b * NPIX;

    {
        uint32_t sf = sb + PV_SF, sh = sb + PV_SH;
        #pragma unroll
        for (int p = 0; p < 4; ++p) {
            int slot = tid + p * 128;
            int r = slot >> 3, ch = slot & 7;
            cp16(sf + swz(r, ch, 128), F + (size_t)r * NPIX + ibase + ch * 8);
            cp16(sh + swz(r, ch, 128), H + (size_t)r * NPIX + ibase + ch * 8);
        }
        if (tid < 16) cp16(sb + PV_SQ + tid * 16, Q + ibase + tid * 4);
        CP_COMMIT();
    }
    #pragma unroll
    for (int p = 0; p < 8; ++p) {
        int slot = tid + p * 128;
        int r = slot >> 4, ch = slot & 15;
        uint4 v = *(const uint4*)(G + (size_t)r * NPIX + j0 + ch * 8);
        *(uint4*)(smem + PV_SG + swz(r, ch, 256)) = v;
    }
    __syncthreads();

    float ot[2][8][4] = {};
    for (int it = 0; it < 32; ++it) {
        const int cur = it & 1;
        if (it + 1 < 32) {
            const int i1 = ibase + (it + 1) * 64, nxt = cur ^ 1;
            uint32_t sf = sb + PV_SF + nxt * 8192, sh = sb + PV_SH + nxt * 8192;
            #pragma unroll
            for (int p = 0; p < 4; ++p) {
                int slot = tid + p * 128;
                int r = slot >> 3, ch = slot & 7;
                cp16(sf + swz(r, ch, 128), F + (size_t)r * NPIX + i1 + ch * 8);
                cp16(sh + swz(r, ch, 128), H + (size_t)r * NPIX + i1 + ch * 8);
            }
            if (tid < 16) cp16(sb + PV_SQ + nxt * 256 + tid * 16, Q + i1 + tid * 4);
            CP_COMMIT();
            CP_WAIT(1);
        } else {
            CP_WAIT(0);
        }
        __syncthreads();

        const uint32_t sFu = sb + PV_SF + cur * 8192;
        const uint32_t sHu = sb + PV_SH + cur * 8192;
        const float* sq = (const float*)(smem + PV_SQ + cur * 256);

        float st[2][8][4] = {};
        #pragma unroll
        for (int kk = 0; kk < 4; ++kk) {
            uint32_t agg[2][4];
            #pragma unroll
            for (int jh = 0; jh < 2; ++jh) {
                int row = kk * 16 + (lane & 7) + ((lane >> 4) & 1) * 8;
                int ch = ((wid * 32 + jh * 16) >> 3) + ((lane >> 3) & 1);
                ldsm_x4_t(agg[jh], sb + PV_SG + swz(row, ch, 256));
            }
            #pragma unroll
            for (int ng = 0; ng < 4; ++ng) {
                int row = kk * 16 + (lane & 7) + ((lane >> 3) & 1) * 8;
                int ch = ng * 2 + (lane >> 4);
                uint32_t bf[4];
                ldsm_x4_t(bf, sFu + swz(row, ch, 128));
                #pragma unroll
                for (int jh = 0; jh < 2; ++jh) {
                    mma16816(st[jh][ng * 2],     agg[jh], bf[0], bf[1]);
                    mma16816(st[jh][ng * 2 + 1], agg[jh], bf[2], bf[3]);
                }
            }
        }
        uint32_t aet[2][4][4];
        #pragma unroll
        for (int jh = 0; jh < 2; ++jh) {
            #pragma unroll
            for (int t = 0; t < 8; ++t) {
                int col = t * 8 + 2 * (lane & 3);
                float q0 = sq[col], q1 = sq[col + 1];
                uint32_t lo = ex2h2(pack2(st[jh][t][0] - q0, st[jh][t][1] - q1));
                uint32_t hi = ex2h2(pack2(st[jh][t][2] - q0, st[jh][t][3] - q1));
                aet[jh][t >> 1][(t & 1) * 2]     = lo;
                aet[jh][t >> 1][(t & 1) * 2 + 1] = hi;
            }
        }
        #pragma unroll
        for (int kt = 0; kt < 4; ++kt) {
            #pragma unroll
            for (int cg = 0; cg < 4; ++cg) {
                int row = cg * 16 + ((lane >> 4) & 1) * 8 + (lane & 7);
                int ch = kt * 2 + ((lane >> 3) & 1);
                uint32_t bh[4];
                ldsm_x4(bh, sHu + swz(row, ch, 128));
                #pragma unroll
                for (int jh = 0; jh < 2; ++jh) {
                    mma16816(ot[jh][cg * 2],     aet[jh][kt], bh[0], bh[1]);
                    mma16816(ot[jh][cg * 2 + 1], aet[jh][kt], bh[2], bh[3]);
                }
            }
        }
        __syncthreads();
    }
    #pragma unroll
    for (int jh = 0; jh < 2; ++jh) {
        int j = j0 + wid * 32 + jh * 16 + (lane >> 2);
        __half* dst = g_attp + ((size_t)(ksp * 4 + b) * NPIX + j) * CP;
        #pragma unroll
        for (int t = 0; t < 8; ++t) {
            int c = t * 8 + 2 * (lane & 3);
            *(uint32_t*)(dst + c)          = pack2(ot[jh][t][0], ot[jh][t][1]);
            *(uint32_t*)(dst + 8 * CP + c) = pack2(ot[jh][t][2], ot[jh][t][3]);
        }
    }
}

// ---------------- final (HMMA): y = gamma * (Wv16 @ (P0+P1)) + x ----------------
// grid (64 j-tiles, 4 c128-tiles, 4 b), 256 thr. smem: sA 16K (c128 x k64) + sB 8K (j64 x k64)
__global__ __launch_bounds__(256) void final_kernel(const float* __restrict__ x,
                                                    const float* __restrict__ gamma,
                                                    float* __restrict__ y)
{
    __shared__ __align__(16) __half sA[128 * 64];
    __shared__ __align__(16) __half sB[64 * 64];
    const int b = blockIdx.z, c0 = blockIdx.y * 128, n0 = blockIdx.x * 64;
    const int tid = threadIdx.x, lane = tid & 31, wid = tid >> 5;  // 8 warps: c16 each
    const uint32_t sAu = smem_u32(sA), sBu = smem_u32(sB);
    const __half* Bv0 = g_attp + (size_t)b * NPIX * CP;
    const __half* Bv1 = g_attp + (size_t)(4 + b) * NPIX * CP;

    // sA: Wv16 rows [c0, c0+128), 64 halves each (rowB 128)
    #pragma unroll
    for (int p = 0; p < 4; ++p) {
        int slot = tid + p * 256;            // 1024 slots
        int r = slot >> 3, ch = slot & 7;
        uint4 v = *(const uint4*)(g_Wv16 + (c0 + r) * CP + ch * 8);
        *(uint4*)((char*)sA + swz(r, ch, 128)) = v;
    }
    // sB: att[j, k] = P0 + P1, rows [n0, n0+64) (rowB 128)
    #pragma unroll
    for (int p = 0; p < 2; ++p) {
        int slot = tid + p * 256;            // 512 slots
        int r = slot >> 3, ch = slot & 7;
        size_t off = (size_t)(n0 + r) * CP + ch * 8;
        uint4 u0 = *(const uint4*)(Bv0 + off);
        uint4 u1 = *(const uint4*)(Bv1 + off);
        uint4 s;
        __half2 h;
        h = __hadd2(*reinterpret_cast<__half2*>(&u0.x), *reinterpret_cast<__half2*>(&u1.x)); s.x = *reinterpret_cast<uint32_t*>(&h);
        h = __hadd2(*reinterpret_cast<__half2*>(&u0.y), *reinterpret_cast<__half2*>(&u1.y)); s.y = *reinterpret_cast<uint32_t*>(&h);
        h = __hadd2(*reinterpret_cast<__half2*>(&u0.z), *reinterpret_cast<__half2*>(&u1.z)); s.z = *reinterpret_cast<uint32_t*>(&h);
        h = __hadd2(*reinterpret_cast<__half2*>(&u0.w), *reinterpret_cast<__half2*>(&u1.w)); s.w = *reinterpret_cast<uint32_t*>(&h);
        *(uint4*)((char*)sB + swz(r, ch, 128)) = s;
    }
    __syncthreads();

    float c[8][4] = {};
    #pragma unroll
    for (int kk = 0; kk < 4; ++kk) {
        uint32_t a[4];
        {
            int row = wid * 16 + (lane & 7) + ((lane >> 3) & 1) * 8;
            int ch = kk * 2 + (lane >> 4);
            ldsm_x4(a, sAu + swz(row, ch, 128));
        }
        #pragma unroll
        for (int ng = 0; ng < 4; ++ng) {
            int row = ng * 16 + ((lane >> 4) & 1) * 8 + (lane & 7);
            int ch = kk * 2 + ((lane >> 3) & 1);
            uint32_t bh[4];
            ldsm_x4(bh, sBu + swz(row, ch, 128));
            mma16816(c[ng * 2],     a, bh[0], bh[1]);
            mma16816(c[ng * 2 + 1], a, bh[2], bh[3]);
        }
    }
    float g = gamma[0];
    int row = c0 + wid * 16 + (lane >> 2);
    #pragma unroll
    for (int t = 0; t < 8; ++t) {
        int col = n0 + (t >> 1) * 16 + (t & 1) * 8 + 2 * (lane & 3);
        size_t o0 = (size_t)b * CIN * NPIX + (size_t)row * NPIX + col;
        size_t o1 = o0 + (size_t)8 * NPIX;
        float2 x0 = *(const float2*)(x + o0);
        float2 x1 = *(const float2*)(x + o1);
        float2 r0, r1;
        r0.x = fmaf(g, c[t][0], x0.x); r0.y = fmaf(g, c[t][1], x0.y);
        r1.x = fmaf(g, c[t][2], x1.x); r1.y = fmaf(g, c[t][3], x1.y);
        *(float2*)(y + o0) = r0;
        *(float2*)(y + o1) = r1;
    }
}

// ---------------- launch ----------------
extern "C" void kernel_launch(void* const* d_in, const int* in_sizes, int n_in,
                              void* d_out, int out_size)
{
    const float* x     = (const float*)d_in[0];
    const float* Wf    = (const float*)d_in[1];
    const float* Wg    = (const float*)d_in[2];
    const float* Wh    = (const float*)d_in[3];
    const float* Wv    = (const float*)d_in[4];
    const float* uf    = (const float*)d_in[5];
    const float* ug    = (const float*)d_in[6];
    const float* uh    = (const float*)d_in[7];
    const float* uv    = (const float*)d_in[8];
    const float* gamma = (const float*)d_in[9];
    float* y = (float*)d_out;

    cudaFuncSetAttribute(proj_kernel, cudaFuncAttributeMaxDynamicSharedMemorySize, PJ_SMEM);
    cudaFuncSetAttribute(pv_kernel,   cudaFuncAttributeMaxDynamicSharedMemorySize, PV_SMEM);

    spectral_kernel<<<4, 512>>>(Wf, Wg, Wh, Wv, uf, ug, uh, uv);
    proj_kernel<<<dim3(32, 4), 256, PJ_SMEM>>>(x);
    stats_kernel<<<dim3(64, 4), 128>>>();
    pv_kernel<<<dim3(32, 4, 2), 128, PV_SMEM>>>();
    final_kernel<<<dim3(64, 4, 4), 256>>>(x, gamma, y);
}